// round 1
// baseline (speedup 1.0000x reference)
#include <cuda_runtime.h>
#include <math.h>

#define B_   2
#define N_   512
#define H_   128
#define NH_  8
#define DH_  16
#define TJ   64
#define WPAD 132

// d_out layout (floats): [x_out | e_out | scores]
#define OFF_EOUT   ((size_t)(B_*N_*H_))                       // 131072
#define OFF_SCORES (OFF_EOUT + (size_t)B_*N_*N_*H_)           // 67239936

// scratch (allocation-free rule -> device globals)
__device__ float g_Q[B_*N_*H_];   // (x@Wq+bq) * 0.25  (1/sqrt(dh) folded)
__device__ float g_K[B_*N_*H_];   // x@Wk+bk  (also V)

// ---------------------------------------------------------------------------
// Kernel A: Q/K projections. grid = B*N rows, 128 threads.
// ---------------------------------------------------------------------------
__global__ void qk_kernel(const float* __restrict__ x,
                          const float* __restrict__ Wq, const float* __restrict__ bq,
                          const float* __restrict__ Wk, const float* __restrict__ bk) {
    __shared__ float xs[H_];
    int row = blockIdx.x;
    int c = threadIdx.x;
    xs[c] = x[row*H_ + c];
    __syncthreads();
    float aq = bq[c], ak = bk[c];
#pragma unroll 8
    for (int k = 0; k < H_; ++k) {
        float xv = xs[k];
        aq = fmaf(xv, Wq[k*H_ + c], aq);
        ak = fmaf(xv, Wk[k*H_ + c], ak);
    }
    g_Q[row*H_ + c] = 0.25f * aq;
    g_K[row*H_ + c] = ak;
}

// ---------------------------------------------------------------------------
// Kernel B: fused  Ee = e@We+be ;  inter = Ee*K_j*Q_i/4 ;  logits = head-sums ;
//                  e_out = inter@Woe+boe.
// grid = B*N blocks (one per (b,i)), 256 threads, loops over 8 j-tiles of 64.
// ---------------------------------------------------------------------------
__global__ __launch_bounds__(256, 1)
void edge_kernel(const float* __restrict__ e,
                 const float* __restrict__ We, const float* __restrict__ be,
                 const float* __restrict__ Woe, const float* __restrict__ boe,
                 float* __restrict__ out) {
    extern __shared__ float sm[];
    float* We_s  = sm;                          // H_*WPAD
    float* Woe_s = We_s + H_*WPAD;              // H_*WPAD
    float* e_s   = Woe_s + H_*WPAD;             // TJ*WPAD  (reused for inter)
    float* k_s   = e_s + TJ*WPAD;               // TJ*WPAD
    float* q_s   = k_s + TJ*WPAD;               // H_
    float* be_s  = q_s + H_;                    // H_
    float* boe_s = be_s + H_;                   // H_

    int row = blockIdx.x;
    int b = row >> 9, i = row & 511;
    int tid = threadIdx.x;

    // Stage weights once (padded rows: stride 132 floats -> conflict-free LDS)
    {
        const float4* We4  = (const float4*)We;
        const float4* Woe4 = (const float4*)Woe;
        for (int idx = tid; idx < H_*(H_/4); idx += 256) {
            int k = idx >> 5, c4 = idx & 31;
            *(float4*)(We_s  + k*WPAD + c4*4) = We4[idx];
            *(float4*)(Woe_s + k*WPAD + c4*4) = Woe4[idx];
        }
        if (tid < H_) {
            q_s[tid]   = g_Q[(b*N_ + i)*H_ + tid];
            be_s[tid]  = be[tid];
            boe_s[tid] = boe[tid];
        }
    }

    // thread tile: 4 rows x 8 cols of the 64x128 output tile
    int tx = tid & 15;          // 16 column groups of 8
    int ty = tid >> 4;          // 16 row groups of 4
    int c0 = tx * 8;
    int r0 = ty * 4;

    for (int jt = 0; jt < N_/TJ; ++jt) {
        int j0 = jt * TJ;
        __syncthreads();        // previous iteration's readers of e_s/k_s done

        // load e tile [TJ,128] and K tile [TJ,128]
        const float4* e4 = (const float4*)(e + (((size_t)(b*N_ + i))*N_ + j0)*H_);
        const float4* K4 = (const float4*)(g_K + ((size_t)b*N_ + j0)*H_);
        for (int idx = tid; idx < TJ*(H_/4); idx += 256) {
            int j = idx >> 5, c4 = idx & 31;
            *(float4*)(e_s + j*WPAD + c4*4) = e4[idx];
            *(float4*)(k_s + j*WPAD + c4*4) = K4[idx];
        }
        __syncthreads();

        // ---- GEMM1: acc = e_tile @ We ----
        float acc[4][8];
#pragma unroll
        for (int rr = 0; rr < 4; ++rr)
#pragma unroll
            for (int cc = 0; cc < 8; ++cc) acc[rr][cc] = 0.f;

#pragma unroll 2
        for (int k = 0; k < H_; ++k) {
            float4 w0 = *(const float4*)(We_s + k*WPAD + c0);
            float4 w1 = *(const float4*)(We_s + k*WPAD + c0 + 4);
            float wv[8] = {w0.x,w0.y,w0.z,w0.w,w1.x,w1.y,w1.z,w1.w};
            float ev[4];
#pragma unroll
            for (int rr = 0; rr < 4; ++rr) ev[rr] = e_s[(r0+rr)*WPAD + k];
#pragma unroll
            for (int rr = 0; rr < 4; ++rr)
#pragma unroll
                for (int cc = 0; cc < 8; ++cc)
                    acc[rr][cc] = fmaf(ev[rr], wv[cc], acc[rr][cc]);
        }

        // ---- bias + elementwise: inter = (Ee+be) * K[j] * Q[i]/4 ----
#pragma unroll
        for (int rr = 0; rr < 4; ++rr) {
            int r = r0 + rr;
#pragma unroll
            for (int cc = 0; cc < 8; ++cc) {
                int c = c0 + cc;
                acc[rr][cc] = (acc[rr][cc] + be_s[c]) * k_s[r*WPAD + c] * q_s[c];
            }
        }
        __syncthreads();        // all GEMM1 reads of e_s complete

        // store inter into e_s (reuse)
#pragma unroll
        for (int rr = 0; rr < 4; ++rr) {
            *(float4*)(e_s + (r0+rr)*WPAD + c0)     =
                make_float4(acc[rr][0], acc[rr][1], acc[rr][2], acc[rr][3]);
            *(float4*)(e_s + (r0+rr)*WPAD + c0 + 4) =
                make_float4(acc[rr][4], acc[rr][5], acc[rr][6], acc[rr][7]);
        }
        __syncthreads();

        // ---- logits: sum inter over each head's 16 dims, write to scores region
        for (int idx = tid; idx < NH_*TJ; idx += 256) {
            int h = idx >> 6, j = idx & 63;            // coalesced over j
            const float* p = e_s + j*WPAD + h*DH_;
            float s = 0.f;
#pragma unroll
            for (int d = 0; d < DH_; ++d) s += p[d];
            out[OFF_SCORES + (((size_t)(b*NH_ + h)*N_ + i)*N_) + j0 + j] = s;
        }

        // ---- GEMM2: e_out = inter @ Woe + boe ----
        float acc2[4][8];
#pragma unroll
        for (int rr = 0; rr < 4; ++rr)
#pragma unroll
            for (int cc = 0; cc < 8; ++cc) acc2[rr][cc] = 0.f;

#pragma unroll 2
        for (int k = 0; k < H_; ++k) {
            float4 w0 = *(const float4*)(Woe_s + k*WPAD + c0);
            float4 w1 = *(const float4*)(Woe_s + k*WPAD + c0 + 4);
            float wv[8] = {w0.x,w0.y,w0.z,w0.w,w1.x,w1.y,w1.z,w1.w};
            float ev[4];
#pragma unroll
            for (int rr = 0; rr < 4; ++rr) ev[rr] = e_s[(r0+rr)*WPAD + k];
#pragma unroll
            for (int rr = 0; rr < 4; ++rr)
#pragma unroll
                for (int cc = 0; cc < 8; ++cc)
                    acc2[rr][cc] = fmaf(ev[rr], wv[cc], acc2[rr][cc]);
        }

        // write e_out tile
#pragma unroll
        for (int rr = 0; rr < 4; ++rr) {
            size_t base = OFF_EOUT +
                (((size_t)(b*N_ + i))*N_ + (size_t)(j0 + r0 + rr))*H_ + c0;
            *(float4*)(out + base) = make_float4(acc2[rr][0] + boe_s[c0+0],
                                                 acc2[rr][1] + boe_s[c0+1],
                                                 acc2[rr][2] + boe_s[c0+2],
                                                 acc2[rr][3] + boe_s[c0+3]);
            *(float4*)(out + base + 4) = make_float4(acc2[rr][4] + boe_s[c0+4],
                                                     acc2[rr][5] + boe_s[c0+5],
                                                     acc2[rr][6] + boe_s[c0+6],
                                                     acc2[rr][7] + boe_s[c0+7]);
        }
    }
}

// ---------------------------------------------------------------------------
// Kernel C: in-place softmax over j (adds attention_mask).
// grid = B*NH*N rows, 256 threads (2 elems each).
// ---------------------------------------------------------------------------
__global__ void softmax_kernel(const float* __restrict__ mask, float* __restrict__ out) {
    int rowid = blockIdx.x;                // (b*NH + h)*N + i
    int i  = rowid & 511;
    int b  = rowid >> 12;                  // rowid / (NH_*N_) = rowid / 4096
    float* p = out + OFF_SCORES + (size_t)rowid * N_;
    const float* mp = mask + ((size_t)b*N_ + i)*N_;   // mask[B,1,N,N]
    __shared__ float red[256];
    int t = threadIdx.x;
    float v0 = p[t]       + mp[t];
    float v1 = p[t + 256] + mp[t + 256];
    red[t] = fmaxf(v0, v1);
    __syncthreads();
    for (int s = 128; s > 0; s >>= 1) {
        if (t < s) red[t] = fmaxf(red[t], red[t+s]);
        __syncthreads();
    }
    float m = red[0];
    __syncthreads();
    float e0 = expf(v0 - m), e1 = expf(v1 - m);
    red[t] = e0 + e1;
    __syncthreads();
    for (int s = 128; s > 0; s >>= 1) {
        if (t < s) red[t] += red[t+s];
        __syncthreads();
    }
    float inv = 1.f / red[0];
    p[t]       = e0 * inv;
    p[t + 256] = e1 * inv;
}

// ---------------------------------------------------------------------------
// Kernel D: att = scores @ V (=K) ;  x_out = att @ Woh + boh.
// grid = B*N blocks (one per (b,i)), 128 threads.
// ---------------------------------------------------------------------------
__global__ void out_kernel(const float* __restrict__ Woh, const float* __restrict__ boh,
                           float* __restrict__ out) {
    __shared__ float sc[NH_][N_];     // 16 KB
    __shared__ float att_s[H_];
    int row = blockIdx.x;
    int b = row >> 9, i = row & 511;
    int t = threadIdx.x;

    const float* sp = out + OFF_SCORES;
    for (int idx = t; idx < NH_*N_; idx += 128) {
        int h = idx >> 9, j = idx & 511;
        sc[h][j] = sp[(((size_t)(b*NH_ + h)*N_ + i)*N_) + j];
    }
    __syncthreads();

    int h = t >> 4;                   // head of column t
    float acc = 0.f;
    const float* kp = g_K + (size_t)b*N_*H_ + t;
#pragma unroll 4
    for (int j = 0; j < N_; ++j)
        acc = fmaf(sc[h][j], kp[(size_t)j*H_], acc);
    att_s[t] = acc;
    __syncthreads();

    float o = boh[t];
#pragma unroll 8
    for (int k = 0; k < H_; ++k)
        o = fmaf(att_s[k], Woh[k*H_ + t], o);
    out[(size_t)row*H_ + t] = o;
}

// ---------------------------------------------------------------------------
extern "C" void kernel_launch(void* const* d_in, const int* in_sizes, int n_in,
                              void* d_out, int out_size) {
    const float* x    = (const float*)d_in[0];
    const float* e    = (const float*)d_in[1];
    const float* mask = (const float*)d_in[2];
    const float* Wq   = (const float*)d_in[3];
    const float* bq   = (const float*)d_in[4];
    const float* Wk   = (const float*)d_in[5];
    const float* bk   = (const float*)d_in[6];
    const float* We   = (const float*)d_in[7];
    const float* be   = (const float*)d_in[8];
    const float* Woh  = (const float*)d_in[9];
    const float* boh  = (const float*)d_in[10];
    const float* Woe  = (const float*)d_in[11];
    const float* boe  = (const float*)d_in[12];
    float* out = (float*)d_out;

    // 2*128*132 + 2*64*132 + 3*128 floats = 204,288 bytes
    int smemB = (2*H_*WPAD + 2*TJ*WPAD + 3*H_) * (int)sizeof(float);
    cudaFuncSetAttribute(edge_kernel, cudaFuncAttributeMaxDynamicSharedMemorySize, smemB);

    qk_kernel<<<B_*N_, H_>>>(x, Wq, bq, Wk, bk);
    edge_kernel<<<B_*N_, 256, smemB>>>(e, We, be, Woe, boe, out);
    softmax_kernel<<<B_*NH_*N_, 256>>>(mask, out);
    out_kernel<<<B_*N_, H_>>>(Woh, boh, out);
}

// round 5
// speedup vs baseline: 2.7690x; 2.7690x over previous
#include <cuda_runtime.h>
#include <cuda_bf16.h>
#include <cstdint>
#include <math.h>

#define B_   2
#define N_   512
#define H_   128
#define NH_  8
#define TJ   64

#define OFF_EOUT   ((size_t)(B_*N_*H_))
#define OFF_SCORES (OFF_EOUT + (size_t)B_*N_*N_*H_)

// ---- smem layout (bytes) for edge kernel ----
// weight parts: rows = output col c (transposed), 128 rows x 288B (k-permuted)
#define WPART   36864            // 128*288
#define SM_W    0                // WeH | WeL | WoH | WoL
#define SM_T0   147456           // tile buf0: hi(64*288) | lo(64*288)
#define SM_T1   184320
#define TLO     18432            // lo offset within a tile buffer
#define SM_Q    221184
#define SM_BE   221696
#define SM_BOE  222208
#define SM_TOTAL 222720

#define RSTRIDE 288              // bytes per row (128 bf16 data + 16 pad)

__device__ float g_Q[B_*N_*H_];   // (x@Wq+bq) * 0.25
__device__ float g_K[B_*N_*H_];   // x@Wk+bk  (= V)
__device__ __align__(16) unsigned char g_Wimg[4*WPART];

// k-permutation within each 16-wide chunk: storage index s for k-position r
// s layout: [0,1,8,9, 2,3,10,11, 4,5,12,13, 6,7,14,15]
static __device__ __host__ __forceinline__ int kperm(int r) {
    return (r < 8) ? ((r >> 1) * 4 + (r & 1)) : (((r & 7) >> 1) * 4 + 2 + (r & 1));
}

static __device__ __forceinline__ uint32_t pk2(__nv_bfloat16 a, __nv_bfloat16 b) {
    __nv_bfloat162 t = __halves2bfloat162(a, b);
    return *(uint32_t*)&t;
}

static __device__ __forceinline__ void mma16816(float* c,
        uint32_t a0, uint32_t a1, uint32_t a2, uint32_t a3,
        uint32_t b0, uint32_t b1) {
    asm volatile(
        "mma.sync.aligned.m16n8k16.row.col.f32.bf16.bf16.f32 "
        "{%0,%1,%2,%3},{%4,%5,%6,%7},{%8,%9},{%0,%1,%2,%3};"
        : "+f"(c[0]), "+f"(c[1]), "+f"(c[2]), "+f"(c[3])
        : "r"(a0), "r"(a1), "r"(a2), "r"(a3), "r"(b0), "r"(b1));
}

// ---------------------------------------------------------------------------
// prep: transpose + bf16 hi/lo split of We, Woe into permuted padded image
// ---------------------------------------------------------------------------
__global__ void prep_kernel(const float* __restrict__ We, const float* __restrict__ Woe,
                            const float* __restrict__ be, const float* __restrict__ boe,
                            float* __restrict__ gbe, float* __restrict__ gboe) {
    int idx = blockIdx.x * 256 + threadIdx.x;   // 16384
    int c = idx >> 7, k = idx & 127;
    int byt = c * RSTRIDE + (k >> 4) * 32 + kperm(k & 15) * 2;
    float we = We[k*H_ + c];
    float wo = Woe[k*H_ + c];
    __nv_bfloat16 weh = __float2bfloat16(we);
    __nv_bfloat16 wel = __float2bfloat16(we - __bfloat162float(weh));
    __nv_bfloat16 woh = __float2bfloat16(wo);
    __nv_bfloat16 wol = __float2bfloat16(wo - __bfloat162float(woh));
    *(__nv_bfloat16*)(g_Wimg + byt)           = weh;
    *(__nv_bfloat16*)(g_Wimg + WPART + byt)   = wel;
    *(__nv_bfloat16*)(g_Wimg + 2*WPART + byt) = woh;
    *(__nv_bfloat16*)(g_Wimg + 3*WPART + byt) = wol;
    if (idx < H_) { gbe[idx] = be[idx]; gboe[idx] = boe[idx]; }
}
__device__ float g_be[H_];
__device__ float g_boe[H_];

// ---------------------------------------------------------------------------
// Q/K projections
// ---------------------------------------------------------------------------
__global__ void qk_kernel(const float* __restrict__ x,
                          const float* __restrict__ Wq, const float* __restrict__ bq,
                          const float* __restrict__ Wk, const float* __restrict__ bk) {
    __shared__ float xs[H_];
    int row = blockIdx.x;
    int c = threadIdx.x;
    xs[c] = x[row*H_ + c];
    __syncthreads();
    float aq = bq[c], ak = bk[c];
#pragma unroll 8
    for (int k = 0; k < H_; ++k) {
        float xv = xs[k];
        aq = fmaf(xv, Wq[k*H_ + c], aq);
        ak = fmaf(xv, Wk[k*H_ + c], ak);
    }
    g_Q[row*H_ + c] = 0.25f * aq;
    g_K[row*H_ + c] = ak;
}

// ---------------------------------------------------------------------------
// edge kernel: mma.sync bf16-split  GEMM1 -> inter/logits -> GEMM2
// ---------------------------------------------------------------------------
static __device__ __forceinline__ void gemm_tile(const char* sm,
        int aHi, int aLo, int bHi, int bLo,
        int m0, int n0, int g, int t, float (&acc)[2][4][4]) {
#pragma unroll
    for (int ks = 0; ks < 8; ++ks) {
        int ao = ks * 32 + 8 * t;
        uint2 AH[2][2], AL[2][2], BH[4], BL[4];
#pragma unroll
        for (int mf = 0; mf < 2; ++mf) {
            int r = (m0 + mf*16 + g) * RSTRIDE + ao;
            AH[mf][0] = *(const uint2*)(sm + aHi + r);
            AH[mf][1] = *(const uint2*)(sm + aHi + r + 8*RSTRIDE);
            AL[mf][0] = *(const uint2*)(sm + aLo + r);
            AL[mf][1] = *(const uint2*)(sm + aLo + r + 8*RSTRIDE);
        }
#pragma unroll
        for (int nf = 0; nf < 4; ++nf) {
            int r = (n0 + nf*8 + g) * RSTRIDE + ao;
            BH[nf] = *(const uint2*)(sm + bHi + r);
            BL[nf] = *(const uint2*)(sm + bLo + r);
        }
#pragma unroll
        for (int mf = 0; mf < 2; ++mf)
#pragma unroll
            for (int nf = 0; nf < 4; ++nf) {
                mma16816(acc[mf][nf], AH[mf][0].x, AH[mf][1].x, AH[mf][0].y, AH[mf][1].y,
                         BH[nf].x, BH[nf].y);
                mma16816(acc[mf][nf], AL[mf][0].x, AL[mf][1].x, AL[mf][0].y, AL[mf][1].y,
                         BH[nf].x, BH[nf].y);
                mma16816(acc[mf][nf], AH[mf][0].x, AH[mf][1].x, AH[mf][0].y, AH[mf][1].y,
                         BL[nf].x, BL[nf].y);
            }
    }
}

static __device__ __forceinline__ void split_store_tile(char* smem, int buf,
        const float4* pref, int tid) {
#pragma unroll
    for (int l = 0; l < 8; ++l) {
        int u = tid + (l << 8);
        int j = u >> 5, kq = u & 31;
        int chunk = kq >> 2, rr = (kq & 3) * 4;
        int s1 = (rr < 8) ? rr*2 : rr*2 - 14;
        int s2 = (rr + 2 < 8) ? (rr+2)*2 : (rr+2)*2 - 14;
        int base = buf + j*RSTRIDE + chunk*32;
        float4 v = pref[l];
        __nv_bfloat16 h0 = __float2bfloat16(v.x);
        __nv_bfloat16 h1 = __float2bfloat16(v.y);
        __nv_bfloat16 h2 = __float2bfloat16(v.z);
        __nv_bfloat16 h3 = __float2bfloat16(v.w);
        __nv_bfloat16 l0 = __float2bfloat16(v.x - __bfloat162float(h0));
        __nv_bfloat16 l1 = __float2bfloat16(v.y - __bfloat162float(h1));
        __nv_bfloat16 l2 = __float2bfloat16(v.z - __bfloat162float(h2));
        __nv_bfloat16 l3 = __float2bfloat16(v.w - __bfloat162float(h3));
        *(uint32_t*)(smem + base + s1*2)       = pk2(h0, h1);
        *(uint32_t*)(smem + base + s2*2)       = pk2(h2, h3);
        *(uint32_t*)(smem + base + TLO + s1*2) = pk2(l0, l1);
        *(uint32_t*)(smem + base + TLO + s2*2) = pk2(l2, l3);
    }
}

__global__ __launch_bounds__(256, 1)
void edge_kernel(const float* __restrict__ e, float* __restrict__ out) {
    extern __shared__ char smem[];
    int tid = threadIdx.x, wid = tid >> 5, lane = tid & 31;
    int g = lane >> 2, t = lane & 3;
    int mi = wid & 1, ni = wid >> 1;
    int m0 = mi * 32, n0 = ni * 32;
    int row = blockIdx.x, b = row >> 9, i = row & 511;

    // stage weights (147,456 B) + per-row vectors
    {
        const float4* w4 = (const float4*)g_Wimg;
        float4* d4 = (float4*)smem;
#pragma unroll
        for (int u = tid; u < 9216; u += 256) d4[u] = w4[u];
    }
    if (tid < H_) {
        ((float*)(smem + SM_Q))[tid]   = g_Q[(b*N_ + i)*H_ + tid];
        ((float*)(smem + SM_BE))[tid]  = g_be[tid];
        ((float*)(smem + SM_BOE))[tid] = g_boe[tid];
    }

    const float* Kb = g_K + (size_t)b * N_ * H_;
    const float* ebase = e + (((size_t)(b*N_ + i)) * N_) * H_;

    // first tile
    {
        float4 pref[8];
        const float4* esrc = (const float4*)ebase;
#pragma unroll
        for (int l = 0; l < 8; ++l) pref[l] = esrc[tid + (l << 8)];
        split_store_tile(smem, SM_T0, pref, tid);
    }
    __syncthreads();

    int bufX = SM_T0, bufY = SM_T1;
    float acc[2][4][4];

    for (int jt = 0; jt < 8; ++jt) {
        int j0 = jt << 6;

        float4 pref[8];
        if (jt < 7) {
            const float4* esrc = (const float4*)(ebase + (size_t)(j0 + TJ) * H_);
#pragma unroll
            for (int l = 0; l < 8; ++l) pref[l] = esrc[tid + (l << 8)];
        }

        // ---- GEMM1: Ee = e @ We ----
#pragma unroll
        for (int mf = 0; mf < 2; ++mf)
#pragma unroll
            for (int nf = 0; nf < 4; ++nf)
#pragma unroll
                for (int q = 0; q < 4; ++q) acc[mf][nf][q] = 0.f;
        gemm_tile(smem, bufX, bufX + TLO, SM_W, SM_W + WPART, m0, n0, g, t, acc);
        __syncthreads();

        // ---- epilogue 1: inter = (Ee+be)*K*Q ; logits ----
        {
            float psum[2][2][2] = {};
#pragma unroll
            for (int mf = 0; mf < 2; ++mf)
#pragma unroll
                for (int nf = 0; nf < 4; ++nf) {
                    int c = n0 + nf*8 + 2*t;
                    float2 q2  = *(const float2*)((const float*)(smem + SM_Q)  + c);
                    float2 be2 = *(const float2*)((const float*)(smem + SM_BE) + c);
                    int jl = m0 + mf*16 + g;
                    float2 k0 = *(const float2*)(Kb + (size_t)(j0 + jl)*H_ + c);
                    float2 k1 = *(const float2*)(Kb + (size_t)(j0 + jl + 8)*H_ + c);
                    float v0 = (acc[mf][nf][0] + be2.x) * k0.x * q2.x;
                    float v1 = (acc[mf][nf][1] + be2.y) * k0.y * q2.y;
                    float v2 = (acc[mf][nf][2] + be2.x) * k1.x * q2.x;
                    float v3 = (acc[mf][nf][3] + be2.y) * k1.y * q2.y;
                    psum[mf][0][nf >> 1] += v0 + v1;
                    psum[mf][1][nf >> 1] += v2 + v3;
                    // store inter hi/lo into bufX (A layout, permuted k)
                    int chunk = c >> 4;
                    int soff = (nf & 1) ? (4*t + 2)*2 : (4*t)*2;
                    int basel = bufX + jl*RSTRIDE + chunk*32 + soff;
                    int baseh = basel + 8*RSTRIDE;
                    __nv_bfloat16 h0 = __float2bfloat16(v0);
                    __nv_bfloat16 h1 = __float2bfloat16(v1);
                    __nv_bfloat16 h2 = __float2bfloat16(v2);
                    __nv_bfloat16 h3 = __float2bfloat16(v3);
                    *(uint32_t*)(smem + basel) = pk2(h0, h1);
                    *(uint32_t*)(smem + baseh) = pk2(h2, h3);
                    *(uint32_t*)(smem + basel + TLO) =
                        pk2(__float2bfloat16(v0 - __bfloat162float(h0)),
                            __float2bfloat16(v1 - __bfloat162float(h1)));
                    *(uint32_t*)(smem + baseh + TLO) =
                        pk2(__float2bfloat16(v2 - __bfloat162float(h2)),
                            __float2bfloat16(v3 - __bfloat162float(h3)));
                }
            // head-sum reduce over t lanes, write logits
#pragma unroll
            for (int mf = 0; mf < 2; ++mf)
#pragma unroll
                for (int half = 0; half < 2; ++half)
#pragma unroll
                    for (int hl = 0; hl < 2; ++hl) {
                        float s = psum[mf][half][hl];
                        s += __shfl_xor_sync(0xffffffffu, s, 1);
                        s += __shfl_xor_sync(0xffffffffu, s, 2);
                        if (t == 0) {
                            int j = m0 + mf*16 + g + half*8;
                            int h = (n0 >> 4) + hl;
                            out[OFF_SCORES + (((size_t)(b*NH_ + h)*N_ + i) << 9) + j0 + j] = s;
                        }
                    }
        }
        __syncthreads();

        // ---- GEMM2: e_out = inter @ Woe ----
#pragma unroll
        for (int mf = 0; mf < 2; ++mf)
#pragma unroll
            for (int nf = 0; nf < 4; ++nf)
#pragma unroll
                for (int q = 0; q < 4; ++q) acc[mf][nf][q] = 0.f;
        gemm_tile(smem, bufX, bufX + TLO, SM_W + 2*WPART, SM_W + 3*WPART, m0, n0, g, t, acc);
        __syncthreads();

        // store prefetched next tile into the other buffer
        if (jt < 7) split_store_tile(smem, bufY, pref, tid);

        // ---- epilogue 2: e_out writes ----
#pragma unroll
        for (int mf = 0; mf < 2; ++mf)
#pragma unroll
            for (int nf = 0; nf < 4; ++nf) {
                int c = n0 + nf*8 + 2*t;
                float2 bo2 = *(const float2*)((const float*)(smem + SM_BOE) + c);
                int jl = m0 + mf*16 + g;
                size_t rb = OFF_EOUT + (((size_t)(b*N_ + i))*N_ + j0 + jl)*H_ + c;
                float2 o0 = make_float2(acc[mf][nf][0] + bo2.x, acc[mf][nf][1] + bo2.y);
                float2 o1 = make_float2(acc[mf][nf][2] + bo2.x, acc[mf][nf][3] + bo2.y);
                *(float2*)(out + rb)          = o0;
                *(float2*)(out + rb + 8*H_)   = o1;
            }
        __syncthreads();

        int tmp = bufX; bufX = bufY; bufY = tmp;
    }
}

// ---------------------------------------------------------------------------
// softmax over j (in place, adds mask)
// ---------------------------------------------------------------------------
__global__ void softmax_kernel(const float* __restrict__ mask, float* __restrict__ out) {
    int rowid = blockIdx.x;
    int i = rowid & 511;
    int b = rowid >> 12;
    float* p = out + OFF_SCORES + (size_t)rowid * N_;
    const float* mp = mask + ((size_t)b*N_ + i)*N_;
    __shared__ float red[256];
    int t = threadIdx.x;
    float v0 = p[t] + mp[t];
    float v1 = p[t + 256] + mp[t + 256];
    red[t] = fmaxf(v0, v1);
    __syncthreads();
    for (int s = 128; s > 0; s >>= 1) {
        if (t < s) red[t] = fmaxf(red[t], red[t+s]);
        __syncthreads();
    }
    float m = red[0];
    __syncthreads();
    float e0 = expf(v0 - m), e1 = expf(v1 - m);
    red[t] = e0 + e1;
    __syncthreads();
    for (int s = 128; s > 0; s >>= 1) {
        if (t < s) red[t] += red[t+s];
        __syncthreads();
    }
    float inv = 1.f / red[0];
    p[t] = e0 * inv;
    p[t + 256] = e1 * inv;
}

// ---------------------------------------------------------------------------
// out: att = scores @ V(=K) ; x_out = att @ Woh + boh.  4 i-rows per block.
// ---------------------------------------------------------------------------
__global__ __launch_bounds__(512)
void out_kernel(const float* __restrict__ Woh, const float* __restrict__ boh,
                float* __restrict__ out) {
    __shared__ float kt[TJ*H_];
    __shared__ float scs[4][NH_][TJ];
    __shared__ float att_s[4][H_];
    int blk = blockIdx.x;
    int b = blk >> 7, i0 = (blk & 127) << 2;
    int t = threadIdx.x, il = t >> 7, c = t & 127, h = c >> 4;
    const float* sp = out + OFF_SCORES;
    float acc = 0.f;
    for (int jt = 0; jt < 8; ++jt) {
        int j0 = jt << 6;
        __syncthreads();
        const float4* K4 = (const float4*)(g_K + ((size_t)b*N_ + j0)*H_);
        for (int u = t; u < 2048; u += 512) ((float4*)kt)[u] = K4[u];
        for (int u = t; u < 2048; u += 512) {
            int ii = u >> 9, hh = (u >> 6) & 7, jj = u & 63;
            scs[ii][hh][jj] = sp[(((size_t)(b*NH_ + hh)*N_) + i0 + ii)*N_ + j0 + jj];
        }
        __syncthreads();
        float a0 = 0.f, a1 = 0.f;
#pragma unroll 4
        for (int j = 0; j < TJ; j += 2) {
            a0 = fmaf(scs[il][h][j],     kt[j*H_ + c],     a0);
            a1 = fmaf(scs[il][h][j + 1], kt[(j+1)*H_ + c], a1);
        }
        acc += a0 + a1;
    }
    att_s[il][c] = acc;
    __syncthreads();
    float o = boh[c];
#pragma unroll 8
    for (int k = 0; k < H_; ++k)
        o = fmaf(att_s[il][k], Woh[k*H_ + c], o);
    out[((size_t)(b*N_) + i0 + il)*H_ + c] = o;
}

// ---------------------------------------------------------------------------
extern "C" void kernel_launch(void* const* d_in, const int* in_sizes, int n_in,
                              void* d_out, int out_size) {
    const float* x    = (const float*)d_in[0];
    const float* e    = (const float*)d_in[1];
    const float* mask = (const float*)d_in[2];
    const float* Wq   = (const float*)d_in[3];
    const float* bq   = (const float*)d_in[4];
    const float* Wk   = (const float*)d_in[5];
    const float* bk   = (const float*)d_in[6];
    const float* We   = (const float*)d_in[7];
    const float* be   = (const float*)d_in[8];
    const float* Woh  = (const float*)d_in[9];
    const float* boh  = (const float*)d_in[10];
    const float* Woe  = (const float*)d_in[11];
    const float* boe  = (const float*)d_in[12];
    float* out = (float*)d_out;

    cudaFuncSetAttribute(edge_kernel, cudaFuncAttributeMaxDynamicSharedMemorySize, SM_TOTAL);

    float *gbe, *gboe;
    cudaGetSymbolAddress((void**)&gbe,  g_be);
    cudaGetSymbolAddress((void**)&gboe, g_boe);

    prep_kernel<<<64, 256>>>(We, Woe, be, boe, gbe, gboe);
    qk_kernel<<<B_*N_, H_>>>(x, Wq, bq, Wk, bk);
    edge_kernel<<<B_*N_, 256, SM_TOTAL>>>(e, out);
    softmax_kernel<<<B_*NH_*N_, 256>>>(mask, out);
    out_kernel<<<B_*128, 512>>>(Woh, boh, out);
}

// round 6
// speedup vs baseline: 3.2214x; 1.1634x over previous
#include <cuda_runtime.h>
#include <cuda_bf16.h>
#include <cstdint>
#include <math.h>

#define B_   2
#define N_   512
#define H_   128
#define NH_  8
#define TJ   64

#define OFF_EOUT   ((size_t)(B_*N_*H_))
#define OFF_SCORES (OFF_EOUT + (size_t)B_*N_*N_*H_)

// ---- smem layout (bytes) ----
// weights: 4 parts (WeH, WeL, WoH, WoL), each 128 rows x 256B, XOR-swizzled
#define SM_W    0
#define WPART   32768
#define SM_T0   131072          // tile buf0: hi 16KB | lo 16KB
#define SM_T1   163840
#define TLOFF   16384
#define SM_LOG  196608          // logits [8][512] f32 = 16KB
#define SM_Q    212992
#define SM_BE   213504
#define SM_BOE  214016
#define SM_TOTAL 214528

__device__ float g_Q[B_*N_*H_];   // (x@Wq+bq)*0.25
__device__ float g_K[B_*N_*H_];   // x@Wk+bk (= V)
__device__ float g_be[H_];
__device__ float g_boe[H_];
__device__ __align__(16) unsigned char g_Wimg[4*WPART];

static __device__ __forceinline__ uint32_t smem_u32(const void* p) {
    uint32_t a;
    asm("{ .reg .u64 t; cvta.to.shared.u64 t, %1; cvt.u32.u64 %0, t; }" : "=r"(a) : "l"(p));
    return a;
}
static __device__ __forceinline__ uint32_t pk2(__nv_bfloat16 a, __nv_bfloat16 b) {
    __nv_bfloat162 t = __halves2bfloat162(a, b);
    return *(uint32_t*)&t;
}
static __device__ __forceinline__ void mma16816(float* c,
        uint32_t a0, uint32_t a1, uint32_t a2, uint32_t a3,
        uint32_t b0, uint32_t b1) {
    asm volatile(
        "mma.sync.aligned.m16n8k16.row.col.f32.bf16.bf16.f32 "
        "{%0,%1,%2,%3},{%4,%5,%6,%7},{%8,%9},{%0,%1,%2,%3};"
        : "+f"(c[0]), "+f"(c[1]), "+f"(c[2]), "+f"(c[3])
        : "r"(a0), "r"(a1), "r"(a2), "r"(a3), "r"(b0), "r"(b1));
}
#define LDSM4(r, addr) \
    asm volatile("ldmatrix.sync.aligned.m8n8.x4.shared.b16 {%0,%1,%2,%3}, [%4];" \
        : "=r"((r)[0]), "=r"((r)[1]), "=r"((r)[2]), "=r"((r)[3]) : "r"(addr))

// phys byte offset within a tile: row*256 + ((k/8 ^ (row&7))*16) + (k&7)*2
static __device__ __host__ __forceinline__ int tswz(int row, int k) {
    return row*256 + ((((k>>3) ^ (row&7)))<<4) + (k&7)*2;
}

// ---------------------------------------------------------------------------
// prep: transpose + bf16 hi/lo split of We, Woe into swizzled image
// ---------------------------------------------------------------------------
__global__ void prep_kernel(const float* __restrict__ We, const float* __restrict__ Woe,
                            const float* __restrict__ be, const float* __restrict__ boe) {
    int idx = blockIdx.x * 256 + threadIdx.x;   // 16384
    int c = idx >> 7, k = idx & 127;
    int byt = tswz(c, k);
    float we = We[k*H_ + c];
    float wo = Woe[k*H_ + c];
    __nv_bfloat16 weh = __float2bfloat16(we);
    __nv_bfloat16 wel = __float2bfloat16(we - __bfloat162float(weh));
    __nv_bfloat16 woh = __float2bfloat16(wo);
    __nv_bfloat16 wol = __float2bfloat16(wo - __bfloat162float(woh));
    *(__nv_bfloat16*)(g_Wimg + byt)           = weh;
    *(__nv_bfloat16*)(g_Wimg + WPART + byt)   = wel;
    *(__nv_bfloat16*)(g_Wimg + 2*WPART + byt) = woh;
    *(__nv_bfloat16*)(g_Wimg + 3*WPART + byt) = wol;
    if (idx < H_) { g_be[idx] = be[idx]; g_boe[idx] = boe[idx]; }
}

// ---------------------------------------------------------------------------
// Q/K projections
// ---------------------------------------------------------------------------
__global__ void qk_kernel(const float* __restrict__ x,
                          const float* __restrict__ Wq, const float* __restrict__ bq,
                          const float* __restrict__ Wk, const float* __restrict__ bk) {
    __shared__ float xs[H_];
    int row = blockIdx.x;
    int c = threadIdx.x;
    xs[c] = x[row*H_ + c];
    __syncthreads();
    float aq = bq[c], ak = bk[c];
#pragma unroll 8
    for (int k = 0; k < H_; ++k) {
        float xv = xs[k];
        aq = fmaf(xv, Wq[k*H_ + c], aq);
        ak = fmaf(xv, Wk[k*H_ + c], ak);
    }
    g_Q[row*H_ + c] = 0.25f * aq;
    g_K[row*H_ + c] = ak;
}

// ---------------------------------------------------------------------------
// edge kernel helpers
// ---------------------------------------------------------------------------
static __device__ __forceinline__ void split_store_tile(char* smem, int buf,
        const float4* pref, int tid) {
#pragma unroll
    for (int l = 0; l < 8; ++l) {
        int u = tid + (l << 8);
        int j = u >> 5, kq = u & 31;
        int k4 = kq << 2;
        int base = buf + tswz(j, k4);
        float4 v = pref[l];
        __nv_bfloat16 h0 = __float2bfloat16(v.x);
        __nv_bfloat16 h1 = __float2bfloat16(v.y);
        __nv_bfloat16 h2 = __float2bfloat16(v.z);
        __nv_bfloat16 h3 = __float2bfloat16(v.w);
        __nv_bfloat16 l0 = __float2bfloat16(v.x - __bfloat162float(h0));
        __nv_bfloat16 l1 = __float2bfloat16(v.y - __bfloat162float(h1));
        __nv_bfloat16 l2 = __float2bfloat16(v.z - __bfloat162float(h2));
        __nv_bfloat16 l3 = __float2bfloat16(v.w - __bfloat162float(h3));
        *(uint32_t*)(smem + base)             = pk2(h0, h1);
        *(uint32_t*)(smem + base + 4)         = pk2(h2, h3);
        *(uint32_t*)(smem + base + TLOFF)     = pk2(l0, l1);
        *(uint32_t*)(smem + base + TLOFF + 4) = pk2(l2, l3);
    }
}

// GEMM: C[64x128] += A[64x128] @ B[128x128]^T' with 3-pass bf16 split.
// A at aHi (lo at +TLOFF), B at bHi (lo at +WPART). ldmatrix fragment loads.
static __device__ __forceinline__ void gemm_tile(uint32_t sb, uint32_t aHi, uint32_t bHi,
        uint32_t aR0, uint32_t aR1, int aR7, int khA,
        uint32_t bR0, uint32_t bR1, int bR7, int khB,
        float (&acc)[2][4][4]) {
    uint32_t aLo = aHi + TLOFF, bLo = bHi + WPART;
#pragma unroll
    for (int ks = 0; ks < 8; ++ks) {
        uint32_t swA = (uint32_t)(((((ks << 1) | khA) ^ aR7)) << 4);
        uint32_t swB = (uint32_t)(((((ks << 1) | khB) ^ bR7)) << 4);
        uint32_t ah0[4], ah1[4], al0[4], al1[4];
        uint32_t bhA[4], bhB[4], blA[4], blB[4];
        LDSM4(ah0, sb + aHi + aR0 + swA);
        LDSM4(ah1, sb + aHi + aR1 + swA);
        LDSM4(al0, sb + aLo + aR0 + swA);
        LDSM4(al1, sb + aLo + aR1 + swA);
        LDSM4(bhA, sb + bHi + bR0 + swB);
        LDSM4(bhB, sb + bHi + bR1 + swB);
        LDSM4(blA, sb + bLo + bR0 + swB);
        LDSM4(blB, sb + bLo + bR1 + swB);
#define DO_NF(A, AH, AL, BH, BL, I0, I1)                                    \
        mma16816(A, AH[0],AH[1],AH[2],AH[3], BH[I0], BH[I1]);               \
        mma16816(A, AL[0],AL[1],AL[2],AL[3], BH[I0], BH[I1]);               \
        mma16816(A, AH[0],AH[1],AH[2],AH[3], BL[I0], BL[I1]);
        DO_NF(acc[0][0], ah0, al0, bhA, blA, 0, 1)
        DO_NF(acc[0][1], ah0, al0, bhA, blA, 2, 3)
        DO_NF(acc[0][2], ah0, al0, bhB, blB, 0, 1)
        DO_NF(acc[0][3], ah0, al0, bhB, blB, 2, 3)
        DO_NF(acc[1][0], ah1, al1, bhA, blA, 0, 1)
        DO_NF(acc[1][1], ah1, al1, bhA, blA, 2, 3)
        DO_NF(acc[1][2], ah1, al1, bhB, blB, 0, 1)
        DO_NF(acc[1][3], ah1, al1, bhB, blB, 2, 3)
#undef DO_NF
    }
}

// ---------------------------------------------------------------------------
// edge: GEMM1 -> inter/logits -> GEMM2, fused mask+softmax at end
// ---------------------------------------------------------------------------
__global__ __launch_bounds__(256, 1)
void edge_kernel(const float* __restrict__ e, const float* __restrict__ mask,
                 float* __restrict__ out) {
    extern __shared__ char smem[];
    uint32_t sb = smem_u32(smem);
    int tid = threadIdx.x, wid = tid >> 5, lane = tid & 31;
    int g = lane >> 2, t = lane & 3;
    int mi = wid & 1, ni = wid >> 1;
    int m0 = mi * 32, n0 = ni * 32;
    int row = blockIdx.x, b = row >> 9, i = row & 511;

    {
        const float4* w4 = (const float4*)g_Wimg;
        float4* d4 = (float4*)smem;
#pragma unroll
        for (int u = tid; u < 8192; u += 256) d4[u] = w4[u];
    }
    if (tid < H_) {
        ((float*)(smem + SM_Q))[tid]   = g_Q[(b*N_ + i)*H_ + tid];
        ((float*)(smem + SM_BE))[tid]  = g_be[tid];
        ((float*)(smem + SM_BOE))[tid] = g_boe[tid];
    }

    const float* Kb = g_K + (size_t)b * N_ * H_;
    const float* ebase = e + ((size_t)(b*N_ + i)) * N_ * H_;

    {
        float4 pref[8];
        const float4* esrc = (const float4*)ebase;
#pragma unroll
        for (int l = 0; l < 8; ++l) pref[l] = esrc[tid + (l << 8)];
        split_store_tile(smem, SM_T0, pref, tid);
    }
    __syncthreads();

    // hoisted per-thread column constants
    float2 q2[4], be2[4], bo2[4];
#pragma unroll
    for (int nf = 0; nf < 4; ++nf) {
        int c = n0 + nf*8 + 2*t;
        q2[nf]  = *(const float2*)((const float*)(smem + SM_Q)  + c);
        be2[nf] = *(const float2*)((const float*)(smem + SM_BE) + c);
        bo2[nf] = *(const float2*)((const float*)(smem + SM_BOE) + c);
    }

    // ldmatrix lane addressing
    int aRow = m0 + (lane & 15);
    uint32_t aR0 = (uint32_t)(aRow * 256);
    uint32_t aR1 = (uint32_t)((aRow + 16) * 256);
    int aR7 = aRow & 7;
    int khA = lane >> 4;
    int bSel = ((lane >> 4) & 1) * 8 + (lane & 7);
    uint32_t bR0 = (uint32_t)((n0 + bSel) * 256);
    uint32_t bR1 = (uint32_t)((n0 + 16 + bSel) * 256);
    int bR7 = (n0 + bSel) & 7;
    int khB = (lane >> 3) & 1;

    int bufX = SM_T0, bufY = SM_T1;
    float acc[2][4][4];
    float* logit_s = (float*)(smem + SM_LOG);

    for (int jt = 0; jt < 8; ++jt) {
        int j0 = jt << 6;

        float4 pref[8];
        if (jt < 7) {
            const float4* esrc = (const float4*)(ebase + (size_t)(j0 + TJ) * H_);
#pragma unroll
            for (int l = 0; l < 8; ++l) pref[l] = esrc[tid + (l << 8)];
        }

        // ---- GEMM1: Ee = e @ We ----
#pragma unroll
        for (int mf = 0; mf < 2; ++mf)
#pragma unroll
            for (int nf = 0; nf < 4; ++nf)
#pragma unroll
                for (int q = 0; q < 4; ++q) acc[mf][nf][q] = 0.f;
        gemm_tile(sb, bufX, SM_W, aR0, aR1, aR7, khA, bR0, bR1, bR7, khB, acc);
        __syncthreads();

        // ---- epilogue 1: inter = (Ee+be)*K*Q ; logits ----
        {
            float psum[2][2][2] = {};
#pragma unroll
            for (int mf = 0; mf < 2; ++mf)
#pragma unroll
                for (int nf = 0; nf < 4; ++nf) {
                    int c = n0 + nf*8 + 2*t;
                    int jl = m0 + mf*16 + g;
                    float2 k0 = *(const float2*)(Kb + (size_t)(j0 + jl)*H_ + c);
                    float2 k1 = *(const float2*)(Kb + (size_t)(j0 + jl + 8)*H_ + c);
                    float v0 = (acc[mf][nf][0] + be2[nf].x) * k0.x * q2[nf].x;
                    float v1 = (acc[mf][nf][1] + be2[nf].y) * k0.y * q2[nf].y;
                    float v2 = (acc[mf][nf][2] + be2[nf].x) * k1.x * q2[nf].x;
                    float v3 = (acc[mf][nf][3] + be2[nf].y) * k1.y * q2[nf].y;
                    psum[mf][0][nf >> 1] += v0 + v1;
                    psum[mf][1][nf >> 1] += v2 + v3;
                    int sw = (((c >> 3) ^ g) << 4) + 4*t;
                    int a0 = bufX + jl*256 + sw;
                    int a1 = bufX + (jl + 8)*256 + sw;
                    __nv_bfloat16 h0 = __float2bfloat16(v0);
                    __nv_bfloat16 h1 = __float2bfloat16(v1);
                    __nv_bfloat16 h2 = __float2bfloat16(v2);
                    __nv_bfloat16 h3 = __float2bfloat16(v3);
                    *(uint32_t*)(smem + a0) = pk2(h0, h1);
                    *(uint32_t*)(smem + a1) = pk2(h2, h3);
                    *(uint32_t*)(smem + a0 + TLOFF) =
                        pk2(__float2bfloat16(v0 - __bfloat162float(h0)),
                            __float2bfloat16(v1 - __bfloat162float(h1)));
                    *(uint32_t*)(smem + a1 + TLOFF) =
                        pk2(__float2bfloat16(v2 - __bfloat162float(h2)),
                            __float2bfloat16(v3 - __bfloat162float(h3)));
                }
#pragma unroll
            for (int mf = 0; mf < 2; ++mf)
#pragma unroll
                for (int half = 0; half < 2; ++half)
#pragma unroll
                    for (int hl = 0; hl < 2; ++hl) {
                        float s = psum[mf][half][hl];
                        s += __shfl_xor_sync(0xffffffffu, s, 1);
                        s += __shfl_xor_sync(0xffffffffu, s, 2);
                        if (t == 0) {
                            int j = m0 + mf*16 + g + half*8;
                            logit_s[(2*ni + hl)*N_ + j0 + j] = s;
                        }
                    }
        }
        __syncthreads();

        // ---- GEMM2: e_out = inter @ Woe ----
#pragma unroll
        for (int mf = 0; mf < 2; ++mf)
#pragma unroll
            for (int nf = 0; nf < 4; ++nf)
#pragma unroll
                for (int q = 0; q < 4; ++q) acc[mf][nf][q] = 0.f;
        gemm_tile(sb, bufX, SM_W + 2*WPART, aR0, aR1, aR7, khA, bR0, bR1, bR7, khB, acc);
        __syncthreads();

        if (jt < 7) split_store_tile(smem, bufY, pref, tid);

        // ---- epilogue 2: e_out writes ----
#pragma unroll
        for (int mf = 0; mf < 2; ++mf)
#pragma unroll
            for (int nf = 0; nf < 4; ++nf) {
                int c = n0 + nf*8 + 2*t;
                int jl = m0 + mf*16 + g;
                size_t rb = OFF_EOUT + (((size_t)(b*N_ + i))*N_ + j0 + jl)*H_ + c;
                *(float2*)(out + rb) =
                    make_float2(acc[mf][nf][0] + bo2[nf].x, acc[mf][nf][1] + bo2[nf].y);
                *(float2*)(out + rb + 8*H_) =
                    make_float2(acc[mf][nf][2] + bo2[nf].x, acc[mf][nf][3] + bo2[nf].y);
            }
        __syncthreads();

        int tmp = bufX; bufX = bufY; bufY = tmp;
    }

    // ---- fused mask + softmax: warp w handles head w ----
    {
        const float* lg = logit_s + wid * N_;
        const float* mrow = mask + ((size_t)b*N_ + i)*N_;
        float4 vv[4];
        float mx = -3.4e38f;
#pragma unroll
        for (int c4 = 0; c4 < 4; ++c4) {
            int j = c4*128 + lane*4;
            float4 lv = *(const float4*)(lg + j);
            float4 mv = *(const float4*)(mrow + j);
            float4 v = make_float4(lv.x + mv.x, lv.y + mv.y, lv.z + mv.z, lv.w + mv.w);
            vv[c4] = v;
            mx = fmaxf(mx, fmaxf(fmaxf(v.x, v.y), fmaxf(v.z, v.w)));
        }
#pragma unroll
        for (int o = 16; o > 0; o >>= 1)
            mx = fmaxf(mx, __shfl_xor_sync(0xffffffffu, mx, o));
        float sum = 0.f;
#pragma unroll
        for (int c4 = 0; c4 < 4; ++c4) {
            vv[c4].x = expf(vv[c4].x - mx);
            vv[c4].y = expf(vv[c4].y - mx);
            vv[c4].z = expf(vv[c4].z - mx);
            vv[c4].w = expf(vv[c4].w - mx);
            sum += vv[c4].x + vv[c4].y + vv[c4].z + vv[c4].w;
        }
#pragma unroll
        for (int o = 16; o > 0; o >>= 1)
            sum += __shfl_xor_sync(0xffffffffu, sum, o);
        float inv = 1.f / sum;
        float* orow = out + OFF_SCORES + (((size_t)(b*NH_ + wid)*N_ + i) << 9);
#pragma unroll
        for (int c4 = 0; c4 < 4; ++c4) {
            int j = c4*128 + lane*4;
            *(float4*)(orow + j) = make_float4(vv[c4].x*inv, vv[c4].y*inv,
                                               vv[c4].z*inv, vv[c4].w*inv);
        }
    }
}

// ---------------------------------------------------------------------------
// out: att = scores @ V(=K) ; x_out = att @ Woh + boh.  4 i-rows per block.
// ---------------------------------------------------------------------------
__global__ __launch_bounds__(512)
void out_kernel(const float* __restrict__ Woh, const float* __restrict__ boh,
                float* __restrict__ out) {
    __shared__ float kt[TJ*H_];
    __shared__ float scs[4][NH_][TJ];
    __shared__ float att_s[4][H_];
    int blk = blockIdx.x;
    int b = blk >> 7, i0 = (blk & 127) << 2;
    int t = threadIdx.x, il = t >> 7, c = t & 127, h = c >> 4;
    const float* sp = out + OFF_SCORES;
    float acc = 0.f;
    for (int jt = 0; jt < 8; ++jt) {
        int j0 = jt << 6;
        __syncthreads();
        const float4* K4 = (const float4*)(g_K + ((size_t)b*N_ + j0)*H_);
        for (int u = t; u < 2048; u += 512) ((float4*)kt)[u] = K4[u];
        for (int u = t; u < 2048; u += 512) {
            int ii = u >> 9, hh = (u >> 6) & 7, jj = u & 63;
            scs[ii][hh][jj] = sp[(((size_t)(b*NH_ + hh)*N_) + i0 + ii)*N_ + j0 + jj];
        }
        __syncthreads();
        float a0 = 0.f, a1 = 0.f;
#pragma unroll 4
        for (int j = 0; j < TJ; j += 2) {
            a0 = fmaf(scs[il][h][j],     kt[j*H_ + c],     a0);
            a1 = fmaf(scs[il][h][j + 1], kt[(j+1)*H_ + c], a1);
        }
        acc += a0 + a1;
    }
    att_s[il][c] = acc;
    __syncthreads();
    float o = boh[c];
#pragma unroll 8
    for (int k = 0; k < H_; ++k)
        o = fmaf(att_s[il][k], Woh[k*H_ + c], o);
    out[((size_t)(b*N_) + i0 + il)*H_ + c] = o;
}

// ---------------------------------------------------------------------------
extern "C" void kernel_launch(void* const* d_in, const int* in_sizes, int n_in,
                              void* d_out, int out_size) {
    const float* x    = (const float*)d_in[0];
    const float* e    = (const float*)d_in[1];
    const float* mask = (const float*)d_in[2];
    const float* Wq   = (const float*)d_in[3];
    const float* bq   = (const float*)d_in[4];
    const float* Wk   = (const float*)d_in[5];
    const float* bk   = (const float*)d_in[6];
    const float* We   = (const float*)d_in[7];
    const float* be   = (const float*)d_in[8];
    const float* Woh  = (const float*)d_in[9];
    const float* boh  = (const float*)d_in[10];
    const float* Woe  = (const float*)d_in[11];
    const float* boe  = (const float*)d_in[12];
    float* out = (float*)d_out;

    cudaFuncSetAttribute(edge_kernel, cudaFuncAttributeMaxDynamicSharedMemorySize, SM_TOTAL);

    prep_kernel<<<64, 256>>>(We, Woe, be, boe);
    qk_kernel<<<B_*N_, H_>>>(x, Wq, bq, Wk, bk);
    edge_kernel<<<B_*N_, 256, SM_TOTAL>>>(e, mask, out);
    out_kernel<<<B_*128, 512>>>(Woh, boh, out);
}

// round 7
// speedup vs baseline: 5.0901x; 1.5801x over previous
#include <cuda_runtime.h>
#include <cuda_fp16.h>
#include <cstdint>
#include <math.h>

#define B_   2
#define N_   512
#define H_   128
#define NH_  8
#define TJ   64

#define OFF_EOUT   ((size_t)(B_*N_*H_))
#define OFF_SCORES (OFF_EOUT + (size_t)B_*N_*N_*H_)

// ---- smem layout (bytes) ----
// weights: 2 parts (We, Woe) fp16, each 128 rows x 256B, XOR-swizzled
#define SM_W    0
#define WPARTH  32768
#define SM_T0   65536           // tile buf0: 16KB fp16
#define SM_T1   81920
#define SM_LOG  98304           // logits [8][512] f32 = 16KB
#define SM_Q    114688
#define SM_BE   115200
#define SM_BOE  115712
#define SM_TOTAL 116224

__device__ float g_Q[B_*N_*H_];   // (x@Wq+bq)*0.25
__device__ float g_K[B_*N_*H_];   // x@Wk+bk (= V)
__device__ float g_be[H_];
__device__ float g_boe[H_];
__device__ __align__(16) unsigned char g_Wimg[2*WPARTH];

static __device__ __forceinline__ uint32_t smem_u32(const void* p) {
    uint32_t a;
    asm("{ .reg .u64 t; cvta.to.shared.u64 t, %1; cvt.u32.u64 %0, t; }" : "=r"(a) : "l"(p));
    return a;
}
static __device__ __forceinline__ uint32_t pk2h(__half a, __half b) {
    __half2 t = __halves2half2(a, b);
    return *(uint32_t*)&t;
}
static __device__ __forceinline__ void mma16816(float* c,
        uint32_t a0, uint32_t a1, uint32_t a2, uint32_t a3,
        uint32_t b0, uint32_t b1) {
    asm volatile(
        "mma.sync.aligned.m16n8k16.row.col.f32.f16.f16.f32 "
        "{%0,%1,%2,%3},{%4,%5,%6,%7},{%8,%9},{%0,%1,%2,%3};"
        : "+f"(c[0]), "+f"(c[1]), "+f"(c[2]), "+f"(c[3])
        : "r"(a0), "r"(a1), "r"(a2), "r"(a3), "r"(b0), "r"(b1));
}
#define LDSM4(r, addr) \
    asm volatile("ldmatrix.sync.aligned.m8n8.x4.shared.b16 {%0,%1,%2,%3}, [%4];" \
        : "=r"((r)[0]), "=r"((r)[1]), "=r"((r)[2]), "=r"((r)[3]) : "r"(addr))

// phys byte offset within a tile: row*256 + ((k/8 ^ (row&7))*16) + (k&7)*2
static __device__ __host__ __forceinline__ int tswz(int row, int k) {
    return row*256 + ((((k>>3) ^ (row&7)))<<4) + (k&7)*2;
}

// ---------------------------------------------------------------------------
// prep: transpose + fp16 convert of We, Woe into swizzled image
// ---------------------------------------------------------------------------
__global__ void prep_kernel(const float* __restrict__ We, const float* __restrict__ Woe,
                            const float* __restrict__ be, const float* __restrict__ boe) {
    int idx = blockIdx.x * 256 + threadIdx.x;   // 16384
    int c = idx >> 7, k = idx & 127;
    int byt = tswz(c, k);
    *(__half*)(g_Wimg + byt)          = __float2half(We[k*H_ + c]);
    *(__half*)(g_Wimg + WPARTH + byt) = __float2half(Woe[k*H_ + c]);
    if (idx < H_) { g_be[idx] = be[idx]; g_boe[idx] = boe[idx]; }
}

// ---------------------------------------------------------------------------
// Q/K projections
// ---------------------------------------------------------------------------
__global__ void qk_kernel(const float* __restrict__ x,
                          const float* __restrict__ Wq, const float* __restrict__ bq,
                          const float* __restrict__ Wk, const float* __restrict__ bk) {
    __shared__ float xs[H_];
    int row = blockIdx.x;
    int c = threadIdx.x;
    xs[c] = x[row*H_ + c];
    __syncthreads();
    float aq = bq[c], ak = bk[c];
#pragma unroll 8
    for (int k = 0; k < H_; ++k) {
        float xv = xs[k];
        aq = fmaf(xv, Wq[k*H_ + c], aq);
        ak = fmaf(xv, Wk[k*H_ + c], ak);
    }
    g_Q[row*H_ + c] = 0.25f * aq;
    g_K[row*H_ + c] = ak;
}

// ---------------------------------------------------------------------------
// edge helpers
// ---------------------------------------------------------------------------
static __device__ __forceinline__ void store_tile(char* smem, int buf,
        const float4* pref, int tid) {
#pragma unroll
    for (int l = 0; l < 8; ++l) {
        int u = tid + (l << 8);
        int j = u >> 5, kq = u & 31;
        int k4 = kq << 2;
        int base = buf + tswz(j, k4);
        float4 v = pref[l];
        *(uint2*)(smem + base) = make_uint2(
            pk2h(__float2half(v.x), __float2half(v.y)),
            pk2h(__float2half(v.z), __float2half(v.w)));
    }
}

// C[64x128] += A[64x128] @ B[128x128]^T, fp16 single pass, ldmatrix loads
static __device__ __forceinline__ void gemm_tile(uint32_t sb, uint32_t aB, uint32_t bB,
        uint32_t aR0, uint32_t aR1, int aR7, int khA,
        uint32_t bR0, uint32_t bR1, int bR7, int khB,
        float (&acc)[2][4][4]) {
#pragma unroll
    for (int ks = 0; ks < 8; ++ks) {
        uint32_t swA = (uint32_t)((((ks << 1) | khA) ^ aR7) << 4);
        uint32_t swB = (uint32_t)((((ks << 1) | khB) ^ bR7) << 4);
        uint32_t a0[4], a1[4], b0[4], b1[4];
        LDSM4(a0, sb + aB + aR0 + swA);
        LDSM4(a1, sb + aB + aR1 + swA);
        LDSM4(b0, sb + bB + bR0 + swB);
        LDSM4(b1, sb + bB + bR1 + swB);
        mma16816(acc[0][0], a0[0],a0[1],a0[2],a0[3], b0[0], b0[1]);
        mma16816(acc[0][1], a0[0],a0[1],a0[2],a0[3], b0[2], b0[3]);
        mma16816(acc[0][2], a0[0],a0[1],a0[2],a0[3], b1[0], b1[1]);
        mma16816(acc[0][3], a0[0],a0[1],a0[2],a0[3], b1[2], b1[3]);
        mma16816(acc[1][0], a1[0],a1[1],a1[2],a1[3], b0[0], b0[1]);
        mma16816(acc[1][1], a1[0],a1[1],a1[2],a1[3], b0[2], b0[3]);
        mma16816(acc[1][2], a1[0],a1[1],a1[2],a1[3], b1[0], b1[1]);
        mma16816(acc[1][3], a1[0],a1[1],a1[2],a1[3], b1[2], b1[3]);
    }
}

// ---------------------------------------------------------------------------
// edge: GEMM1 -> inter/logits -> GEMM2, fused mask+softmax at end
// ---------------------------------------------------------------------------
__global__ __launch_bounds__(256, 1)
void edge_kernel(const float* __restrict__ e, const float* __restrict__ mask,
                 float* __restrict__ out) {
    extern __shared__ char smem[];
    uint32_t sb = smem_u32(smem);
    int tid = threadIdx.x, wid = tid >> 5, lane = tid & 31;
    int g = lane >> 2, t = lane & 3;
    int mi = wid & 1, ni = wid >> 1;
    int m0 = mi * 32, n0 = ni * 32;
    int row = blockIdx.x, b = row >> 9, i = row & 511;

    {
        const float4* w4 = (const float4*)g_Wimg;
        float4* d4 = (float4*)smem;
#pragma unroll
        for (int u = tid; u < 4096; u += 256) d4[u] = w4[u];
    }
    if (tid < H_) {
        ((float*)(smem + SM_Q))[tid]   = g_Q[(b*N_ + i)*H_ + tid];
        ((float*)(smem + SM_BE))[tid]  = g_be[tid];
        ((float*)(smem + SM_BOE))[tid] = g_boe[tid];
    }

    const float* Kb = g_K + (size_t)b * N_ * H_;
    const float* ebase = e + ((size_t)(b*N_ + i)) * N_ * H_;

    {
        float4 pref[8];
        const float4* esrc = (const float4*)ebase;
#pragma unroll
        for (int l = 0; l < 8; ++l) pref[l] = esrc[tid + (l << 8)];
        store_tile(smem, SM_T0, pref, tid);
    }
    __syncthreads();

    float2 q2[4], be2[4], bo2[4];
#pragma unroll
    for (int nf = 0; nf < 4; ++nf) {
        int c = n0 + nf*8 + 2*t;
        q2[nf]  = *(const float2*)((const float*)(smem + SM_Q)  + c);
        be2[nf] = *(const float2*)((const float*)(smem + SM_BE) + c);
        bo2[nf] = *(const float2*)((const float*)(smem + SM_BOE) + c);
    }

    // ldmatrix lane addressing (identical to validated r6 scheme)
    int aRow = m0 + (lane & 15);
    uint32_t aR0 = (uint32_t)(aRow * 256);
    uint32_t aR1 = (uint32_t)((aRow + 16) * 256);
    int aR7 = aRow & 7;
    int khA = lane >> 4;
    int bSel = ((lane >> 4) & 1) * 8 + (lane & 7);
    uint32_t bR0 = (uint32_t)((n0 + bSel) * 256);
    uint32_t bR1 = (uint32_t)((n0 + 16 + bSel) * 256);
    int bR7 = (n0 + bSel) & 7;
    int khB = (lane >> 3) & 1;

    int bufX = SM_T0, bufY = SM_T1;
    float acc[2][4][4];
    float* logit_s = (float*)(smem + SM_LOG);

    for (int jt = 0; jt < 8; ++jt) {
        int j0 = jt << 6;

        float4 pref[8];
        if (jt < 7) {
            const float4* esrc = (const float4*)(ebase + (size_t)(j0 + TJ) * H_);
#pragma unroll
            for (int l = 0; l < 8; ++l) pref[l] = esrc[tid + (l << 8)];
        }

        // ---- GEMM1: Ee = e @ We ----
#pragma unroll
        for (int mf = 0; mf < 2; ++mf)
#pragma unroll
            for (int nf = 0; nf < 4; ++nf)
#pragma unroll
                for (int q = 0; q < 4; ++q) acc[mf][nf][q] = 0.f;
        gemm_tile(sb, bufX, SM_W, aR0, aR1, aR7, khA, bR0, bR1, bR7, khB, acc);
        __syncthreads();

        // ---- epilogue 1: inter = (Ee+be)*K*Q ; logits ; store inter fp16 ----
        {
            float psum[2][2][2] = {};
#pragma unroll
            for (int mf = 0; mf < 2; ++mf)
#pragma unroll
                for (int nf = 0; nf < 4; ++nf) {
                    int c = n0 + nf*8 + 2*t;
                    int jl = m0 + mf*16 + g;
                    float2 k0 = *(const float2*)(Kb + (size_t)(j0 + jl)*H_ + c);
                    float2 k1 = *(const float2*)(Kb + (size_t)(j0 + jl + 8)*H_ + c);
                    float v0 = (acc[mf][nf][0] + be2[nf].x) * k0.x * q2[nf].x;
                    float v1 = (acc[mf][nf][1] + be2[nf].y) * k0.y * q2[nf].y;
                    float v2 = (acc[mf][nf][2] + be2[nf].x) * k1.x * q2[nf].x;
                    float v3 = (acc[mf][nf][3] + be2[nf].y) * k1.y * q2[nf].y;
                    psum[mf][0][nf >> 1] += v0 + v1;
                    psum[mf][1][nf >> 1] += v2 + v3;
                    int sw = (((c >> 3) ^ g) << 4) + 4*t;
                    *(uint32_t*)(smem + bufX + jl*256 + sw) =
                        pk2h(__float2half(v0), __float2half(v1));
                    *(uint32_t*)(smem + bufX + (jl + 8)*256 + sw) =
                        pk2h(__float2half(v2), __float2half(v3));
                }
#pragma unroll
            for (int mf = 0; mf < 2; ++mf)
#pragma unroll
                for (int half = 0; half < 2; ++half)
#pragma unroll
                    for (int hl = 0; hl < 2; ++hl) {
                        float s = psum[mf][half][hl];
                        s += __shfl_xor_sync(0xffffffffu, s, 1);
                        s += __shfl_xor_sync(0xffffffffu, s, 2);
                        if (t == 0) {
                            int j = m0 + mf*16 + g + half*8;
                            logit_s[(2*ni + hl)*N_ + j0 + j] = s;
                        }
                    }
        }
        __syncthreads();

        // ---- GEMM2: e_out = inter @ Woe ----
#pragma unroll
        for (int mf = 0; mf < 2; ++mf)
#pragma unroll
            for (int nf = 0; nf < 4; ++nf)
#pragma unroll
                for (int q = 0; q < 4; ++q) acc[mf][nf][q] = 0.f;
        gemm_tile(sb, bufX, SM_W + WPARTH, aR0, aR1, aR7, khA, bR0, bR1, bR7, khB, acc);
        __syncthreads();

        if (jt < 7) store_tile(smem, bufY, pref, tid);

        // ---- epilogue 2: e_out writes ----
#pragma unroll
        for (int mf = 0; mf < 2; ++mf)
#pragma unroll
            for (int nf = 0; nf < 4; ++nf) {
                int c = n0 + nf*8 + 2*t;
                int jl = m0 + mf*16 + g;
                size_t rb = OFF_EOUT + (((size_t)(b*N_ + i))*N_ + j0 + jl)*H_ + c;
                *(float2*)(out + rb) =
                    make_float2(acc[mf][nf][0] + bo2[nf].x, acc[mf][nf][1] + bo2[nf].y);
                *(float2*)(out + rb + 8*H_) =
                    make_float2(acc[mf][nf][2] + bo2[nf].x, acc[mf][nf][3] + bo2[nf].y);
            }
        __syncthreads();

        int tmp = bufX; bufX = bufY; bufY = tmp;
    }

    // ---- fused mask + softmax: warp w handles head w ----
    {
        const float* lg = logit_s + wid * N_;
        const float* mrow = mask + ((size_t)b*N_ + i)*N_;
        float4 vv[4];
        float mx = -3.4e38f;
#pragma unroll
        for (int c4 = 0; c4 < 4; ++c4) {
            int j = c4*128 + lane*4;
            float4 lv = *(const float4*)(lg + j);
            float4 mv = *(const float4*)(mrow + j);
            float4 v = make_float4(lv.x + mv.x, lv.y + mv.y, lv.z + mv.z, lv.w + mv.w);
            vv[c4] = v;
            mx = fmaxf(mx, fmaxf(fmaxf(v.x, v.y), fmaxf(v.z, v.w)));
        }
#pragma unroll
        for (int o = 16; o > 0; o >>= 1)
            mx = fmaxf(mx, __shfl_xor_sync(0xffffffffu, mx, o));
        float sum = 0.f;
#pragma unroll
        for (int c4 = 0; c4 < 4; ++c4) {
            vv[c4].x = expf(vv[c4].x - mx);
            vv[c4].y = expf(vv[c4].y - mx);
            vv[c4].z = expf(vv[c4].z - mx);
            vv[c4].w = expf(vv[c4].w - mx);
            sum += vv[c4].x + vv[c4].y + vv[c4].z + vv[c4].w;
        }
#pragma unroll
        for (int o = 16; o > 0; o >>= 1)
            sum += __shfl_xor_sync(0xffffffffu, sum, o);
        float inv = 1.f / sum;
        float* orow = out + OFF_SCORES + (((size_t)(b*NH_ + wid)*N_ + i) << 9);
#pragma unroll
        for (int c4 = 0; c4 < 4; ++c4) {
            int j = c4*128 + lane*4;
            *(float4*)(orow + j) = make_float4(vv[c4].x*inv, vv[c4].y*inv,
                                               vv[c4].z*inv, vv[c4].w*inv);
        }
    }
}

// ---------------------------------------------------------------------------
// out: att = scores @ V(=K) ; x_out = att @ Woh + boh. One block per (b,i).
// ---------------------------------------------------------------------------
__global__ __launch_bounds__(256)
void out_kernel(const float* __restrict__ Woh, const float* __restrict__ boh,
                float* __restrict__ out) {
    __shared__ float sc[NH_*N_];     // 16KB
    __shared__ float red[256];
    __shared__ float att_s[H_];
    int blk = blockIdx.x;
    int b = blk >> 9, i = blk & 511;
    int tid = threadIdx.x;

    const float* sp = out + OFF_SCORES;
    for (int u = tid; u < NH_*N_; u += 256) {
        int h = u >> 9, j = u & 511;
        sc[u] = sp[(((size_t)(b*NH_ + h)*N_ + i) << 9) + j];
    }
    __syncthreads();

    int c = tid & 127, t2 = tid >> 7, h = c >> 4;
    const float* kp = g_K + (((size_t)b*N_) + t2*256)*H_ + c;
    const float* srow = sc + h*N_ + t2*256;
    float a0 = 0.f, a1 = 0.f;
#pragma unroll 8
    for (int j = 0; j < 256; j += 2) {
        a0 = fmaf(srow[j],     kp[(size_t)j*H_],       a0);
        a1 = fmaf(srow[j + 1], kp[(size_t)(j+1)*H_],   a1);
    }
    red[tid] = a0 + a1;
    __syncthreads();
    if (tid < H_) att_s[tid] = red[tid] + red[tid + 128];
    __syncthreads();
    if (tid < H_) {
        float o = boh[c];
#pragma unroll 8
        for (int k = 0; k < H_; ++k)
            o = fmaf(att_s[k], Woh[k*H_ + c], o);
        out[((size_t)(b*N_) + i)*H_ + c] = o;
    }
}

// ---------------------------------------------------------------------------
extern "C" void kernel_launch(void* const* d_in, const int* in_sizes, int n_in,
                              void* d_out, int out_size) {
    const float* x    = (const float*)d_in[0];
    const float* e    = (const float*)d_in[1];
    const float* mask = (const float*)d_in[2];
    const float* Wq   = (const float*)d_in[3];
    const float* bq   = (const float*)d_in[4];
    const float* Wk   = (const float*)d_in[5];
    const float* bk   = (const float*)d_in[6];
    const float* We   = (const float*)d_in[7];
    const float* be   = (const float*)d_in[8];
    const float* Woh  = (const float*)d_in[9];
    const float* boh  = (const float*)d_in[10];
    const float* Woe  = (const float*)d_in[11];
    const float* boe  = (const float*)d_in[12];
    float* out = (float*)d_out;

    cudaFuncSetAttribute(edge_kernel, cudaFuncAttributeMaxDynamicSharedMemorySize, SM_TOTAL);

    prep_kernel<<<64, 256>>>(We, Woe, be, boe);
    qk_kernel<<<B_*N_, H_>>>(x, Wq, bq, Wk, bk);
    edge_kernel<<<B_*N_, 256, SM_TOTAL>>>(e, mask, out);
    out_kernel<<<B_*N_, 256>>>(Woh, boh, out);
}